// round 14
// baseline (speedup 1.0000x reference)
#include <cuda_runtime.h>
#include <stdint.h>

// Algebraic feature expansion:
//   out[:, 0:16]    = x
//   out[:, 16:136]  = pair products  x[a]*x[b]   (lex order)
//   out[:, 136:696] = triple products x[a]*x[b]*x[c] (lex order)
// B=262144 rows, 696 out cols. HBM-store + L1tex co-bound in v10.
//
// v14: v10 skeleton (one 16-row tile per block, grid=16384, constant table,
// full 16-row unroll, __stcs) but operands come from the SHUFFLE unit, not
// shared memory: per row each warp does ONE conflict-free LDS to get the row
// into its lanes (lane<16 -> x[lane], lane>=16 -> 1.0 via xs[r][16]), then
// 12 __shfl_sync extract the operands. This removes ~65 of the ~87 L1TEX
// cycles/row, un-throttling the store stream (LDS and STG share L1TEX;
// shuffles run on a separate pipe). All 192 threads stay converged through
// the shuffles; stores are predicated.

#define NC    16
#define NPAIR 120
#define OUTC  696
#define Q4    174          // OUTC / 4
#define RTILE 16           // rows per tile (262144/16 = 16384 blocks)
#define PAD   20           // floats per cached row (16 data + 1.0 @16 + pad)
#define BLK   192          // 6 full warps; threads [0,174) store

// ---- Compile-time packed index table: a | b<<8 | c<<16 (16 = dummy -> 1.0) ----
struct Tab { unsigned v[OUTC]; };

static constexpr Tab make_tab() {
    Tab t{};
    int col = 0;
    for (int a = 0; a < NC; a++)
        t.v[col++] = (unsigned)a | (16u << 8) | (16u << 16);
    for (int a = 0; a < NC; a++)
        for (int b = a + 1; b < NC; b++)
            t.v[col++] = (unsigned)a | ((unsigned)b << 8) | (16u << 16);
    for (int a = 0; a < NC; a++)
        for (int b = a + 1; b < NC; b++)
            for (int c = b + 1; c < NC; c++)
                t.v[col++] = (unsigned)a | ((unsigned)b << 8) | ((unsigned)c << 16);
    return t;
}

__constant__ Tab ctab = make_tab();

__global__ __launch_bounds__(BLK) void algebraic_expand_kernel(
    const float* __restrict__ x,
    float4* __restrict__ out4,
    int nrows)
{
    __shared__ __align__(16) float xs[RTILE][PAD];

    const int t    = threadIdx.x;
    const int lane = t & 31;
    const int row0 = blockIdx.x * RTILE;

    // ---- Kick off the tile load first (LDG in flight during decode) ----
    float4 ld;
    const bool loader = (t < RTILE * NC / 4);     // 64 loader threads
    const int lr = t >> 2;
    const int lc = (t & 3) << 2;
    const bool do_ld = loader && (row0 + lr < nrows);
    if (do_ld)
        ld = reinterpret_cast<const float4*>(x + (size_t)row0 * NC)[t];

    // ---- Decode this thread's fixed chunk from __constant__ (overlaps LDG) ----
    const bool active = (t < Q4);
    int i0 = 16, i1 = 16, i2 = 16, i3 = 16, i4 = 16, i5 = 16,
        i6 = 16, i7 = 16, i8 = 16, i9 = 16, ia = 16, ib = 16;
    if (active) {
        const uint4 pk = reinterpret_cast<const uint4*>(ctab.v)[t];
        i0 =  pk.x        & 255u;  i1 = (pk.x >>  8) & 255u;  i2 = pk.x >> 16;
        i3 =  pk.y        & 255u;  i4 = (pk.y >>  8) & 255u;  i5 = pk.y >> 16;
        i6 =  pk.z        & 255u;  i7 = (pk.z >>  8) & 255u;  i8 = pk.z >> 16;
        i9 =  pk.w        & 255u;  ia = (pk.w >>  8) & 255u;  ib = pk.w >> 16;
    }

    // ---- Stage the tile ----
    if (do_ld)
        *reinterpret_cast<float4*>(&xs[lr][lc]) = ld;
    if (t < RTILE) xs[t][16] = 1.0f;   // dummy operand (src lane 16 -> 1.0)
    __syncthreads();

    // lane source column: lanes 0..15 -> x[lane], lanes 16..31 -> 1.0 slot.
    // Bank check: within a row, cols 0..16 land in 17 distinct banks -> 1 wf.
    const int mycol = (lane < NC) ? lane : NC;

    float4* ob = out4 + (size_t)row0 * Q4 + t;
    const bool fullt = (row0 + RTILE <= nrows);
    const int  rem   = nrows - row0;

    #pragma unroll
    for (int r = 0; r < RTILE; r++) {
        const float rv = xs[r][mycol];           // one LDS per warp per row

        const float a0 = __shfl_sync(0xffffffffu, rv, i0);
        const float a1 = __shfl_sync(0xffffffffu, rv, i1);
        const float a2 = __shfl_sync(0xffffffffu, rv, i2);
        const float a3 = __shfl_sync(0xffffffffu, rv, i3);
        const float a4 = __shfl_sync(0xffffffffu, rv, i4);
        const float a5 = __shfl_sync(0xffffffffu, rv, i5);
        const float a6 = __shfl_sync(0xffffffffu, rv, i6);
        const float a7 = __shfl_sync(0xffffffffu, rv, i7);
        const float a8 = __shfl_sync(0xffffffffu, rv, i8);
        const float a9 = __shfl_sync(0xffffffffu, rv, i9);
        const float aa = __shfl_sync(0xffffffffu, rv, ia);
        const float ab = __shfl_sync(0xffffffffu, rv, ib);

        float4 v;
        v.x = a0 * a1 * a2;
        v.y = a3 * a4 * a5;
        v.z = a6 * a7 * a8;
        v.w = a9 * aa * ab;

        if (active && (fullt || r < rem))
            __stcs(&ob[(size_t)r * Q4], v);
    }
}

extern "C" void kernel_launch(void* const* d_in, const int* in_sizes, int n_in,
                              void* d_out, int out_size)
{
    const float* x = (const float*)d_in[0];
    const int nrows = in_sizes[0] / NC;

    const int nblocks = (nrows + RTILE - 1) / RTILE;   // 16384 for B=262144
    algebraic_expand_kernel<<<nblocks, BLK>>>(x, (float4*)d_out, nrows);
}

// round 15
// speedup vs baseline: 1.0964x; 1.0964x over previous
#include <cuda_runtime.h>
#include <stdint.h>

// Algebraic feature expansion:
//   out[:, 0:16]    = x
//   out[:, 16:136]  = pair products  x[a]*x[b]   (lex order)
//   out[:, 136:696] = triple products x[a]*x[b]*x[c] (lex order)
// B=262144 rows, 696 out cols. HBM-store-bound (~730 MB out).
//
// v15: byte-identical to v10 (best: 102.6us — one 16-row tile per block,
// grid=16384, constant table, 12 LDS + 8 FMUL per chunk, full 16-row unroll,
// __stcs) with ONE change: __launch_bounds__(192, 9) caps regs at ~37 so a
// 9th block fits per SM (1728 threads, occ ~84% vs 70%). More independent
// resident blocks = the one mechanism that has measurably raised DRAM%
// (R9->R10). Body small enough that 40->37 regs should not spill.

#define NC    16
#define NPAIR 120
#define OUTC  696
#define Q4    174          // OUTC / 4
#define RTILE 16           // rows per tile (262144/16 = 16384 blocks)
#define PAD   20           // floats per cached row (16 data + 1.0 dummy + align)
#define BLK   192          // 6 warps; threads [0,174) compute, [0,64) load
#define NBLK  9            // resident blocks per SM target (reg cap ~37)

// ---- Compile-time packed index table: a | b<<8 | c<<16 (16 = dummy -> 1.0) ----
struct Tab { unsigned v[OUTC]; };

static constexpr Tab make_tab() {
    Tab t{};
    int col = 0;
    for (int a = 0; a < NC; a++)
        t.v[col++] = (unsigned)a | (16u << 8) | (16u << 16);
    for (int a = 0; a < NC; a++)
        for (int b = a + 1; b < NC; b++)
            t.v[col++] = (unsigned)a | ((unsigned)b << 8) | (16u << 16);
    for (int a = 0; a < NC; a++)
        for (int b = a + 1; b < NC; b++)
            for (int c = b + 1; c < NC; c++)
                t.v[col++] = (unsigned)a | ((unsigned)b << 8) | ((unsigned)c << 16);
    return t;
}

__constant__ Tab ctab = make_tab();

__global__ __launch_bounds__(BLK, NBLK) void algebraic_expand_kernel(
    const float* __restrict__ x,
    float4* __restrict__ out4,
    int nrows)
{
    __shared__ __align__(16) float xs[RTILE][PAD];

    const int t    = threadIdx.x;
    const int row0 = blockIdx.x * RTILE;

    // ---- Kick off the tile load first (LDG in flight during decode) ----
    float4 ld;
    const bool loader = (t < RTILE * NC / 4);     // 64 loader threads
    const int lr = t >> 2;
    const int lc = (t & 3) << 2;
    const bool do_ld = loader && (row0 + lr < nrows);
    if (do_ld)
        ld = reinterpret_cast<const float4*>(x + (size_t)row0 * NC)[t];

    // ---- Decode this thread's fixed chunk from __constant__ (overlaps LDG) ----
    const bool active = (t < Q4);
    const float* base = &xs[0][0];
    const float *p0 = base, *p1 = base, *p2 = base, *p3 = base,
                *p4 = base, *p5 = base, *p6 = base, *p7 = base,
                *p8 = base, *p9 = base, *pa = base, *pb = base;
    if (active) {
        const uint4 pk = reinterpret_cast<const uint4*>(ctab.v)[t];
        p0 = base + ( pk.x        & 255u);
        p1 = base + ((pk.x >>  8) & 255u);
        p2 = base + ( pk.x >> 16        );
        p3 = base + ( pk.y        & 255u);
        p4 = base + ((pk.y >>  8) & 255u);
        p5 = base + ( pk.y >> 16        );
        p6 = base + ( pk.z        & 255u);
        p7 = base + ((pk.z >>  8) & 255u);
        p8 = base + ( pk.z >> 16        );
        p9 = base + ( pk.w        & 255u);
        pa = base + ((pk.w >>  8) & 255u);
        pb = base + ( pk.w >> 16        );
    }

    // ---- Stage the tile ----
    if (do_ld)
        *reinterpret_cast<float4*>(&xs[lr][lc]) = ld;
    if (t < RTILE) xs[t][16] = 1.0f;   // dummy operand
    __syncthreads();

    if (!active) return;

    float4* ob = out4 + (size_t)row0 * Q4 + t;

    if (row0 + RTILE <= nrows) {
        // fast path: full tile, all offsets compile-time immediates
        #pragma unroll
        for (int r = 0; r < RTILE; r++) {
            const int o = r * PAD;
            float4 v;
            v.x = p0[o] * p1[o] * p2[o];
            v.y = p3[o] * p4[o] * p5[o];
            v.z = p6[o] * p7[o] * p8[o];
            v.w = p9[o] * pa[o] * pb[o];
            __stcs(&ob[(size_t)r * Q4], v);
        }
    } else {
        const int rem = nrows - row0;
        for (int r = 0; r < rem; r++) {
            const int o = r * PAD;
            float4 v;
            v.x = p0[o] * p1[o] * p2[o];
            v.y = p3[o] * p4[o] * p5[o];
            v.z = p6[o] * p7[o] * p8[o];
            v.w = p9[o] * pa[o] * pb[o];
            __stcs(&ob[(size_t)r * Q4], v);
        }
    }
}

extern "C" void kernel_launch(void* const* d_in, const int* in_sizes, int n_in,
                              void* d_out, int out_size)
{
    const float* x = (const float*)d_in[0];
    const int nrows = in_sizes[0] / NC;

    const int nblocks = (nrows + RTILE - 1) / RTILE;   // 16384 for B=262144
    algebraic_expand_kernel<<<nblocks, BLK>>>(x, (float4*)d_out, nrows);
}

// round 16
// speedup vs baseline: 1.1370x; 1.0371x over previous
#include <cuda_runtime.h>
#include <stdint.h>

// Algebraic feature expansion:
//   out[:, 0:16]    = x
//   out[:, 16:136]  = pair products  x[a]*x[b]   (lex order)
//   out[:, 136:696] = triple products x[a]*x[b]*x[c] (lex order)
// B=262144 rows, 696 out cols. HBM-store-bound (~730 MB out).
//
// FINAL (== v10, best measured: 102.6us, 7.27 TB/s effective ~ 91% of spec):
//   - one 16-row tile per block, grid = ntiles = 16384: maximum block-level
//     oversubscription lets the CTA scheduler interleave one block's
//     serialized load phase with other blocks' store bursts (R9/R10/R12/R13
//     mapped this curve; 16384 x 192 is the peak)
//   - compile-time __constant__ index table (zero per-block build cost);
//     each thread owns one fixed float4 output chunk for all 16 rows,
//     operand smem pointers decoded once
//   - per row per thread: 12 LDS (immediate offsets), 8 FMUL, 1 STG.128
//     via __stcs (streaming, keeps L2 clean); full 16-row unroll = natural
//     40-reg codegen with maximal store MLP (caps/partial unrolls all lost)

#define NC    16
#define NPAIR 120
#define OUTC  696
#define Q4    174          // OUTC / 4
#define RTILE 16           // rows per tile (262144/16 = 16384 blocks)
#define PAD   20           // floats per cached row (16 data + 1.0 dummy + align)
#define BLK   192          // 6 warps; threads [0,174) compute, [0,64) load

// ---- Compile-time packed index table: a | b<<8 | c<<16 (16 = dummy -> 1.0) ----
struct Tab { unsigned v[OUTC]; };

static constexpr Tab make_tab() {
    Tab t{};
    int col = 0;
    for (int a = 0; a < NC; a++)
        t.v[col++] = (unsigned)a | (16u << 8) | (16u << 16);
    for (int a = 0; a < NC; a++)
        for (int b = a + 1; b < NC; b++)
            t.v[col++] = (unsigned)a | ((unsigned)b << 8) | (16u << 16);
    for (int a = 0; a < NC; a++)
        for (int b = a + 1; b < NC; b++)
            for (int c = b + 1; c < NC; c++)
                t.v[col++] = (unsigned)a | ((unsigned)b << 8) | ((unsigned)c << 16);
    return t;
}

__constant__ Tab ctab = make_tab();

__global__ __launch_bounds__(BLK) void algebraic_expand_kernel(
    const float* __restrict__ x,
    float4* __restrict__ out4,
    int nrows)
{
    __shared__ __align__(16) float xs[RTILE][PAD];

    const int t    = threadIdx.x;
    const int row0 = blockIdx.x * RTILE;

    // ---- Kick off the tile load first (LDG in flight during decode) ----
    float4 ld;
    const bool loader = (t < RTILE * NC / 4);     // 64 loader threads
    const int lr = t >> 2;
    const int lc = (t & 3) << 2;
    const bool do_ld = loader && (row0 + lr < nrows);
    if (do_ld)
        ld = reinterpret_cast<const float4*>(x + (size_t)row0 * NC)[t];

    // ---- Decode this thread's fixed chunk from __constant__ (overlaps LDG) ----
    const bool active = (t < Q4);
    const float* base = &xs[0][0];
    const float *p0 = base, *p1 = base, *p2 = base, *p3 = base,
                *p4 = base, *p5 = base, *p6 = base, *p7 = base,
                *p8 = base, *p9 = base, *pa = base, *pb = base;
    if (active) {
        const uint4 pk = reinterpret_cast<const uint4*>(ctab.v)[t];
        p0 = base + ( pk.x        & 255u);
        p1 = base + ((pk.x >>  8) & 255u);
        p2 = base + ( pk.x >> 16        );
        p3 = base + ( pk.y        & 255u);
        p4 = base + ((pk.y >>  8) & 255u);
        p5 = base + ( pk.y >> 16        );
        p6 = base + ( pk.z        & 255u);
        p7 = base + ((pk.z >>  8) & 255u);
        p8 = base + ( pk.z >> 16        );
        p9 = base + ( pk.w        & 255u);
        pa = base + ((pk.w >>  8) & 255u);
        pb = base + ( pk.w >> 16        );
    }

    // ---- Stage the tile ----
    if (do_ld)
        *reinterpret_cast<float4*>(&xs[lr][lc]) = ld;
    if (t < RTILE) xs[t][16] = 1.0f;   // dummy operand
    __syncthreads();

    if (!active) return;

    float4* ob = out4 + (size_t)row0 * Q4 + t;

    if (row0 + RTILE <= nrows) {
        // fast path: full tile, all offsets compile-time immediates
        #pragma unroll
        for (int r = 0; r < RTILE; r++) {
            const int o = r * PAD;
            float4 v;
            v.x = p0[o] * p1[o] * p2[o];
            v.y = p3[o] * p4[o] * p5[o];
            v.z = p6[o] * p7[o] * p8[o];
            v.w = p9[o] * pa[o] * pb[o];
            __stcs(&ob[(size_t)r * Q4], v);
        }
    } else {
        const int rem = nrows - row0;
        for (int r = 0; r < rem; r++) {
            const int o = r * PAD;
            float4 v;
            v.x = p0[o] * p1[o] * p2[o];
            v.y = p3[o] * p4[o] * p5[o];
            v.z = p6[o] * p7[o] * p8[o];
            v.w = p9[o] * pa[o] * pb[o];
            __stcs(&ob[(size_t)r * Q4], v);
        }
    }
}

extern "C" void kernel_launch(void* const* d_in, const int* in_sizes, int n_in,
                              void* d_out, int out_size)
{
    const float* x = (const float*)d_in[0];
    const int nrows = in_sizes[0] / NC;

    const int nblocks = (nrows + RTILE - 1) / RTILE;   // 16384 for B=262144
    algebraic_expand_kernel<<<nblocks, BLK>>>(x, (float4*)d_out, nrows);
}

// round 17
// speedup vs baseline: 1.1449x; 1.0069x over previous
#include <cuda_runtime.h>
#include <stdint.h>

// Algebraic feature expansion:
//   out[:, 0:16]    = x
//   out[:, 16:136]  = pair products  x[a]*x[b]   (lex order)
//   out[:, 136:696] = triple products x[a]*x[b]*x[c] (lex order)
// B=262144 rows, 696 out cols. HBM-store-bound (~730 MB out).
//
// FINAL (v10; best measured 102.6us = 7.27 TB/s effective, ~91% of spec):
//   - one 16-row tile per block, grid = ntiles = 16384: maximum block-level
//     oversubscription lets the CTA scheduler interleave one block's
//     serialized load phase with other blocks' store bursts (granularity
//     curve mapped in R9/R10/R12/R13; 16384 x 192 is the peak)
//   - compile-time __constant__ index table (zero per-block build cost);
//     each thread owns one fixed float4 output chunk for all 16 rows,
//     operand smem pointers decoded once
//   - per row per thread: 12 LDS (immediate offsets), 8 FMUL, 1 STG.128
//     via __stcs (streaming); full 16-row unroll = natural 40-reg codegen
//     with maximal store MLP (all caps / partial unrolls / pipelines /
//     shuffle or pair-factoring variants measured slower)

#define NC    16
#define NPAIR 120
#define OUTC  696
#define Q4    174          // OUTC / 4
#define RTILE 16           // rows per tile (262144/16 = 16384 blocks)
#define PAD   20           // floats per cached row (16 data + 1.0 dummy + align)
#define BLK   192          // 6 warps; threads [0,174) compute, [0,64) load

// ---- Compile-time packed index table: a | b<<8 | c<<16 (16 = dummy -> 1.0) ----
struct Tab { unsigned v[OUTC]; };

static constexpr Tab make_tab() {
    Tab t{};
    int col = 0;
    for (int a = 0; a < NC; a++)
        t.v[col++] = (unsigned)a | (16u << 8) | (16u << 16);
    for (int a = 0; a < NC; a++)
        for (int b = a + 1; b < NC; b++)
            t.v[col++] = (unsigned)a | ((unsigned)b << 8) | (16u << 16);
    for (int a = 0; a < NC; a++)
        for (int b = a + 1; b < NC; b++)
            for (int c = b + 1; c < NC; c++)
                t.v[col++] = (unsigned)a | ((unsigned)b << 8) | ((unsigned)c << 16);
    return t;
}

__constant__ Tab ctab = make_tab();

__global__ __launch_bounds__(BLK) void algebraic_expand_kernel(
    const float* __restrict__ x,
    float4* __restrict__ out4,
    int nrows)
{
    __shared__ __align__(16) float xs[RTILE][PAD];

    const int t    = threadIdx.x;
    const int row0 = blockIdx.x * RTILE;

    // ---- Kick off the tile load first (LDG in flight during decode) ----
    float4 ld;
    const bool loader = (t < RTILE * NC / 4);     // 64 loader threads
    const int lr = t >> 2;
    const int lc = (t & 3) << 2;
    const bool do_ld = loader && (row0 + lr < nrows);
    if (do_ld)
        ld = reinterpret_cast<const float4*>(x + (size_t)row0 * NC)[t];

    // ---- Decode this thread's fixed chunk from __constant__ (overlaps LDG) ----
    const bool active = (t < Q4);
    const float* base = &xs[0][0];
    const float *p0 = base, *p1 = base, *p2 = base, *p3 = base,
                *p4 = base, *p5 = base, *p6 = base, *p7 = base,
                *p8 = base, *p9 = base, *pa = base, *pb = base;
    if (active) {
        const uint4 pk = reinterpret_cast<const uint4*>(ctab.v)[t];
        p0 = base + ( pk.x        & 255u);
        p1 = base + ((pk.x >>  8) & 255u);
        p2 = base + ( pk.x >> 16        );
        p3 = base + ( pk.y        & 255u);
        p4 = base + ((pk.y >>  8) & 255u);
        p5 = base + ( pk.y >> 16        );
        p6 = base + ( pk.z        & 255u);
        p7 = base + ((pk.z >>  8) & 255u);
        p8 = base + ( pk.z >> 16        );
        p9 = base + ( pk.w        & 255u);
        pa = base + ((pk.w >>  8) & 255u);
        pb = base + ( pk.w >> 16        );
    }

    // ---- Stage the tile ----
    if (do_ld)
        *reinterpret_cast<float4*>(&xs[lr][lc]) = ld;
    if (t < RTILE) xs[t][16] = 1.0f;   // dummy operand
    __syncthreads();

    if (!active) return;

    float4* ob = out4 + (size_t)row0 * Q4 + t;

    if (row0 + RTILE <= nrows) {
        // fast path: full tile, all offsets compile-time immediates
        #pragma unroll
        for (int r = 0; r < RTILE; r++) {
            const int o = r * PAD;
            float4 v;
            v.x = p0[o] * p1[o] * p2[o];
            v.y = p3[o] * p4[o] * p5[o];
            v.z = p6[o] * p7[o] * p8[o];
            v.w = p9[o] * pa[o] * pb[o];
            __stcs(&ob[(size_t)r * Q4], v);
        }
    } else {
        const int rem = nrows - row0;
        for (int r = 0; r < rem; r++) {
            const int o = r * PAD;
            float4 v;
            v.x = p0[o] * p1[o] * p2[o];
            v.y = p3[o] * p4[o] * p5[o];
            v.z = p6[o] * p7[o] * p8[o];
            v.w = p9[o] * pa[o] * pb[o];
            __stcs(&ob[(size_t)r * Q4], v);
        }
    }
}

extern "C" void kernel_launch(void* const* d_in, const int* in_sizes, int n_in,
                              void* d_out, int out_size)
{
    const float* x = (const float*)d_in[0];
    const int nrows = in_sizes[0] / NC;

    const int nblocks = (nrows + RTILE - 1) / RTILE;   // 16384 for B=262144
    algebraic_expand_kernel<<<nblocks, BLK>>>(x, (float4*)d_out, nrows);
}